// round 4
// baseline (speedup 1.0000x reference)
#include <cuda_runtime.h>
#include <math.h>

typedef unsigned long long ull;

#define SX 18
#define KS 13
#define OS 6
#define NC 3
#define W4 28561
#define W3 2197
#define W2 169
#define X3 5832
#define X2 324
#define XB 104976

// x slab in SMEM: 36 (iy',iz') groups x 18 ix-rows x 18 floats, group stride 326
// (326/2 = 163 odd -> 16 lanes at stride 163 (8B units) hit distinct bank-pairs)
#define GSTRIDE 326
#define SLAB_FLOATS (36 * GSTRIDE)      // 11736
#define WS_FLOATS   (NC * KS * 14)      // 546 (kw padded 13->14 with zero)
#define NTHREADS 224

__device__ __forceinline__ ull ffma2(ull a, ull b, ull c) {
    ull d;
    asm("fma.rn.f32x2 %0, %1, %2, %3;" : "=l"(d) : "l"(a), "l"(b), "l"(c));
    return d;
}

__global__ __launch_bounds__(NTHREADS, 2)
void conv4d_fused2(const float* __restrict__ x, const float* __restrict__ cw,
                   const float* __restrict__ cb, const float* __restrict__ lw,
                   const float* __restrict__ lb, float* __restrict__ out)
{
    __shared__ __align__(16) float slab[SLAB_FLOATS];
    __shared__ __align__(16) float w_s[WS_FLOATS];
    float* red = slab;   // aliased; guarded by __syncthreads() before use

    const int b   = blockIdx.x;
    const int tid = threadIdx.x;
    const bool active = (tid < 216);
    const int par = tid & 1;          // ix parity
    const int p   = tid >> 1;         // (c, oy, oz)
    int c = 0, oy = 0, oz = 0;
    if (active) { c = p / 36; int r = p % 36; oy = r / 6; oz = r % 6; }
    const int g = oy * 6 + oz;

    // acc[ox*6+ow] packed: lo = even-kw partial, hi = odd-kw partial
    ull acc[36];
    #pragma unroll
    for (int i = 0; i < 36; ++i) acc[i] = 0ull;

    const float* xb_ = x + (size_t)b * XB;

    for (int ky = 0; ky < KS; ++ky) {
        for (int kz = 0; kz < KS; ++kz) {
            __syncthreads();   // protect previous slab/w readers

            // ---- stage x slab: coalesced float2 copy ----
            // element u = iz'*18 + iw is contiguous in gmem for fixed (ix, iy')
            for (int t2 = tid; t2 < 5832; t2 += NTHREADS) {
                int ixy = t2 / 54;  int u2 = t2 % 54;
                int ix  = ixy / 6;  int iyp = ixy % 6;
                int izp = u2 / 9;   int iw  = (u2 % 9) * 2;
                const ull* src =
                    (const ull*)(xb_ + ix * X3 + (iyp + ky) * X2 + kz * SX) + u2;
                *(ull*)(slab + (iyp * 6 + izp) * GSTRIDE + ix * SX + iw) = *src;
            }
            // ---- stage weight slab, kw padded to 14 with zero ----
            for (int t = tid; t < WS_FLOATS; t += NTHREADS) {
                int cc = t / 182;  int r = t % 182;
                int kx = r / 14;   int kw = r % 14;
                w_s[t] = (kw < KS)
                       ? cw[cc * W4 + kx * W3 + ky * W2 + kz * KS + kw] : 0.f;
            }
            __syncthreads();

            if (active) {
                const float* grp = slab + g * GSTRIDE;
                #pragma unroll 1
                for (int ixi = 0; ixi < 9; ++ixi) {
                    const int ix = 2 * ixi + par;
                    const ull* row = (const ull*)(grp + ix * SX);
                    ull xpA[9], xpB[9];
                    #pragma unroll
                    for (int j = 0; j < 9; ++j) xpA[j] = row[j];
                    #pragma unroll
                    for (int j = 0; j < 8; ++j)
                        xpB[j] = (xpA[j] >> 32) | (xpA[j + 1] << 32);
                    xpB[8] = xpA[8] >> 32;   // (x[17], 0) — hi pairs with w[13]=0

                    #pragma unroll
                    for (int ox = 0; ox < 6; ++ox) {
                        int kx = ix - ox;
                        if ((unsigned)kx < 13u) {
                            const ull* wp = (const ull*)(w_s + (c * KS + kx) * 14);
                            #pragma unroll
                            for (int kp = 0; kp < 7; ++kp) {
                                ull a = wp[kp];   // (w[2kp], w[2kp+1])
                                acc[ox*6+0] = ffma2(a, xpA[kp],     acc[ox*6+0]);
                                acc[ox*6+1] = ffma2(a, xpB[kp],     acc[ox*6+1]);
                                acc[ox*6+2] = ffma2(a, xpA[kp + 1], acc[ox*6+2]);
                                acc[ox*6+3] = ffma2(a, xpB[kp + 1], acc[ox*6+3]);
                                acc[ox*6+4] = ffma2(a, xpA[kp + 2], acc[ox*6+4]);
                                acc[ox*6+5] = ffma2(a, xpB[kp + 2], acc[ox*6+5]);
                            }
                        }
                    }
                }
            }
        }
    }

    // ---- combine even/odd-kw lanes, then ix-parity partner, then epilogue ----
    float partial = 0.f;
    {
        float s[36];
        #pragma unroll
        for (int i = 0; i < 36; ++i) {
            float lo = __uint_as_float((unsigned)acc[i]);
            float hi = __uint_as_float((unsigned)(acc[i] >> 32));
            s[i] = lo + hi;
        }
        #pragma unroll
        for (int i = 0; i < 36; ++i)
            s[i] += __shfl_xor_sync(0xffffffffu, s[i], 1);

        if (active && par == 0) {
            float bias = __ldg(cb + c);
            #pragma unroll
            for (int ox = 0; ox < 6; ++ox)
                #pragma unroll
                for (int ow = 0; ow < 6; ++ow) {
                    float h = fmaxf(s[ox * 6 + ow] + bias, 0.f);
                    partial = fmaf(h,
                        __ldg(lw + c * 1296 + ox * 216 + oy * 36 + oz * 6 + ow),
                        partial);
                }
        }
    }

    __syncthreads();          // slab reads done everywhere before red aliases it
    red[tid] = partial;
    __syncthreads();
    if (tid < 96) red[tid] += red[tid + 128];
    __syncthreads();
    if (tid < 64) red[tid] += red[tid + 64];
    __syncthreads();
    if (tid < 32) {
        float v = red[tid] + red[tid + 32];
        #pragma unroll
        for (int off = 16; off > 0; off >>= 1)
            v += __shfl_down_sync(0xffffffffu, v, off);
        if (tid == 0) {
            float z = v + __ldg(lb);        // R2 bug: lin_b was dropped here
            out[b] = 1.f / (1.f + expf(-z));
        }
    }
}

extern "C" void kernel_launch(void* const* d_in, const int* in_sizes, int n_in,
                              void* d_out, int out_size)
{
    const float* x      = (const float*)d_in[0];
    const float* conv_w = (const float*)d_in[1];
    const float* conv_b = (const float*)d_in[2];
    const float* lin_w  = (const float*)d_in[3];
    const float* lin_b  = (const float*)d_in[4];
    float* out = (float*)d_out;

    conv4d_fused2<<<512, NTHREADS>>>(x, conv_w, conv_b, lin_w, lin_b, out);
}

// round 7
// speedup vs baseline: 1.7568x; 1.7568x over previous
#include <cuda_runtime.h>
#include <cstdint>
#include <math.h>

#define SX 18
#define KS 13
#define W4 28561
#define W3 2197
#define W2 169
#define X3 5832
#define X2 324
#define XB 104976

#define APITCH 24                 // floats per slab row (k-pad 24, no extra pad)
#define AROWS  656                // 648 used + 8 M-pad reach, all zero-init
#define BPITCH 28                 // floats per B row (n-dim pitch; conflict-free)
#define AWORDS (AROWS * APITCH)               // 15744
#define BWORDS (13 * 24 * BPITCH)             // 9828
#define SMEM_BYTES ((AWORDS + BWORDS) * 4)    // 102288 -> fits 2 blocks/SM

__device__ __forceinline__ uint32_t tf32r(float f) {
    uint32_t r; asm("cvt.rna.tf32.f32 %0, %1;" : "=r"(r) : "f"(f)); return r;
}

// Operand slots per PTX map: a0=A[g][k0], a1=A[g+8][k0], a2=A[g][k1], a3=A[g+8][k1]
// with the consistent k-permutation k0=2*tig, k1=2*tig+1 mirrored in B rows.
__device__ __forceinline__ void mma8(float* c, uint2 alo, uint2 ahi,
                                     const uint32_t* b) {
    asm volatile(
        "mma.sync.aligned.m16n8k8.row.col.f32.tf32.tf32.f32 "
        "{%0,%1,%2,%3}, {%4,%5,%6,%7}, {%8,%9}, {%0,%1,%2,%3};"
        : "+f"(c[0]), "+f"(c[1]), "+f"(c[2]), "+f"(c[3])
        : "r"(alo.x), "r"(ahi.x), "r"(alo.y), "r"(ahi.y),
          "r"(b[0]), "r"(b[1]));
}

__global__ __launch_bounds__(256, 2)
void conv4d_mma(const float* __restrict__ x,  const float* __restrict__ cw,
                const float* __restrict__ cb, const float* __restrict__ lw,
                const float* __restrict__ lb, float* __restrict__ out)
{
    extern __shared__ uint32_t smem[];
    uint32_t* slab = smem;             // A: row = ix*36 + oyz, 24 tf32 cols
    uint32_t* Bs   = smem + AWORDS;    // B: [kx][k(24)][n], pitch 28

    const int b   = blockIdx.x;
    const int tid = threadIdx.x;
    const int wid = tid >> 5;
    const int lid = tid & 31;
    const int g   = lid >> 2;          // groupID (row / n-col group)
    const int tig = lid & 3;           // thread-in-group (k / col pair)
    const bool has2 = (wid < 6);       // warps 0-5 own 2 m-tiles, 6-7 own 1

    // C fragments: [tile][ntile][4], accumulated over all 169 slabs
    float c[2][3][4];
    #pragma unroll
    for (int t = 0; t < 2; ++t)
        #pragma unroll
        for (int n = 0; n < 3; ++n)
            #pragma unroll
            for (int v = 0; v < 4; ++v) c[t][n][v] = 0.f;

    // zero all smem once: zero-pads (A k 18..23, A M-pad rows, B holes) persist
    for (int i = tid; i < AWORDS + BWORDS; i += 256) smem[i] = 0u;
    __syncthreads();

    const float* xb = x + (size_t)b * XB;
    const int m0a = wid * 16, m0b = (wid + 8) * 16;

    #pragma unroll 1
    for (int i = 0; i < 169; ++i) {
        const int ky = i / 13, kz = i % 13;

        // ---- stage A slab: 5832 float2, coalesced-ish, rna->tf32 ----
        #pragma unroll 1
        for (int u = tid; u < 5832; u += 256) {
            int row = u / 9;  int j = u - row * 9;
            int ix  = row / 36; int oyz = row - ix * 36;
            int oy  = oyz / 6;  int oz  = oyz - oy * 6;
            float2 v = *(const float2*)(xb + ix * X3 + (oy + ky) * X2
                                        + (oz + kz) * SX + 2 * j);
            uint2 w; w.x = tf32r(v.x); w.y = tf32r(v.y);
            *(uint2*)(slab + row * APITCH + 2 * j) = w;
        }
        // ---- stage B: 507 weights -> Toeplitz scatter (6 writes each) ----
        #pragma unroll 1
        for (int t = tid; t < 507; t += 256) {
            int kx = t / 39; int r = t - kx * 39;
            int ch = r / 13; int kw = r - ch * 13;
            uint32_t val = tf32r(cw[ch * W4 + kx * W3 + ky * W2 + kz * KS + kw]);
            uint32_t* dst = Bs + kx * (24 * BPITCH) + ch * 6;
            #pragma unroll
            for (int ow = 0; ow < 6; ++ow)
                dst[(kw + ow) * BPITCH + ow] = val;
        }
        __syncthreads();

        // ---- compute: 13 kx x 3 ksteps x (14 m-tiles x 3 n-tiles) ----
        #pragma unroll 1
        for (int kx = 0; kx < 13; ++kx) {
            uint32_t bf[3][3][2];
            const uint32_t* Bk = Bs + kx * (24 * BPITCH) + (2 * tig) * BPITCH + g;
            #pragma unroll
            for (int ks = 0; ks < 3; ++ks)
                #pragma unroll
                for (int nt = 0; nt < 3; ++nt) {
                    bf[ks][nt][0] = Bk[ks * 8 * BPITCH + nt * 8];
                    bf[ks][nt][1] = Bk[ks * 8 * BPITCH + BPITCH + nt * 8];
                }
            #pragma unroll
            for (int t = 0; t < 2; ++t) {
                if (t == 1 && !has2) break;
                const int m0 = (t == 0) ? m0a : m0b;
                const uint32_t* Ar = slab + (m0 + g + 36 * kx) * APITCH + 2 * tig;
                uint2 alo[3], ahi[3];
                #pragma unroll
                for (int ks = 0; ks < 3; ++ks) {
                    alo[ks] = *(const uint2*)(Ar + ks * 8);
                    ahi[ks] = *(const uint2*)(Ar + 8 * APITCH + ks * 8);
                }
                #pragma unroll
                for (int ks = 0; ks < 3; ++ks)
                    #pragma unroll
                    for (int nt = 0; nt < 3; ++nt)
                        mma8(c[t][nt], alo[ks], ahi[ks], bf[ks][nt]);
            }
        }
        __syncthreads();
    }

    // ---- epilogue: bias + ReLU + dot(lin_w), then block reduce ----
    float partial = 0.f;
    #pragma unroll
    for (int t = 0; t < 2; ++t) {
        if (t == 1 && !has2) break;
        const int m0 = (t == 0) ? m0a : m0b;
        #pragma unroll
        for (int nt = 0; nt < 3; ++nt)
            #pragma unroll
            for (int v = 0; v < 4; ++v) {
                int m = m0 + g + (v >> 1) * 8;
                int n = nt * 8 + tig * 2 + (v & 1);
                if (m < 216 && n < 18) {
                    int ox = m / 36; int oyz = m - ox * 36;
                    int ch = n / 6;  int ow  = n - ch * 6;
                    float h = c[t][nt][v] + __ldg(cb + ch);
                    h = fmaxf(h, 0.f);
                    partial = fmaf(h,
                        __ldg(lw + ch * 1296 + ox * 216 + oyz * 6 + ow),
                        partial);
                }
            }
    }

    float* red = (float*)smem;     // slab reads done; reuse as reduction buf
    red[tid] = partial;
    __syncthreads();
    if (tid < 128) red[tid] += red[tid + 128];
    __syncthreads();
    if (tid < 64)  red[tid] += red[tid + 64];
    __syncthreads();
    if (tid < 32) {
        float v = red[tid] + red[tid + 32];
        #pragma unroll
        for (int off = 16; off > 0; off >>= 1)
            v += __shfl_down_sync(0xffffffffu, v, off);
        if (tid == 0) {
            float z = v + __ldg(lb);
            out[b] = 1.f / (1.f + expf(-z));
        }
    }
}

extern "C" void kernel_launch(void* const* d_in, const int* in_sizes, int n_in,
                              void* d_out, int out_size)
{
    const float* x      = (const float*)d_in[0];
    const float* conv_w = (const float*)d_in[1];
    const float* conv_b = (const float*)d_in[2];
    const float* lin_w  = (const float*)d_in[3];
    const float* lin_b  = (const float*)d_in[4];
    float* out = (float*)d_out;

    cudaFuncSetAttribute(conv4d_mma, cudaFuncAttributeMaxDynamicSharedMemorySize,
                         SMEM_BYTES);
    conv4d_mma<<<512, 256, SMEM_BYTES>>>(x, conv_w, conv_b, lin_w, lin_b, out);
}

// round 8
// speedup vs baseline: 2.2200x; 1.2636x over previous
#include <cuda_runtime.h>
#include <cstdint>
#include <math.h>

#define SX 18
#define KS 13
#define W4 28561
#define W3 2197
#define W2 169
#define X3 5832
#define X2 324
#define XB 104976

#define APITCH 24
#define AROWS  656
#define BPITCH 28
#define AWORDS (AROWS * APITCH)               // 15744 words (62.98 KB)
#define BWORDS (13 * 24 * BPITCH)             // 9828 words  (39.31 KB)
#define TOTWORDS (2 * AWORDS + 2 * BWORDS)    // 51144
#define SMEM_BYTES (TOTWORDS * 4)             // 204576 B (< 227 KB)
#define ABYTES (AWORDS * 4)
#define BBASE  (2 * AWORDS)

__device__ __forceinline__ uint32_t tf32r(float f) {
    uint32_t r; asm("cvt.rna.tf32.f32 %0, %1;" : "=r"(r) : "f"(f)); return r;
}
__device__ __forceinline__ uint32_t smem_u32(const void* p) {
    uint32_t a; asm("{ .reg .u64 t; cvta.to.shared.u64 t, %1; cvt.u32.u64 %0, t; }"
                    : "=r"(a) : "l"(p));
    return a;
}
__device__ __forceinline__ void cp8(uint32_t dst, const void* src) {
    asm volatile("cp.async.ca.shared.global [%0], [%1], 8;"
                 :: "r"(dst), "l"(src) : "memory");
}

// a0=A[g][k0], a1=A[g+8][k0], a2=A[g][k1], a3=A[g+8][k1]; k0=2tig,k1=2tig+1
// mirrored in B rows (consistent k-permutation).
__device__ __forceinline__ void mma8(float* c, uint2 alo, uint2 ahi,
                                     const uint32_t* b) {
    asm volatile(
        "mma.sync.aligned.m16n8k8.row.col.f32.tf32.tf32.f32 "
        "{%0,%1,%2,%3}, {%4,%5,%6,%7}, {%8,%9}, {%0,%1,%2,%3};"
        : "+f"(c[0]), "+f"(c[1]), "+f"(c[2]), "+f"(c[3])
        : "r"(alo.x), "r"(ahi.x), "r"(alo.y), "r"(ahi.y),
          "r"(b[0]), "r"(b[1]));
}

__global__ __launch_bounds__(256, 1)
void conv4d_mma_pipe(const float* __restrict__ x,  const float* __restrict__ cw,
                     const float* __restrict__ cb, const float* __restrict__ lw,
                     const float* __restrict__ lb, float* __restrict__ out)
{
    extern __shared__ uint32_t smem[];
    const uint32_t sbase = smem_u32(smem);

    const int b   = blockIdx.x;
    const int tid = threadIdx.x;
    const int wid = tid >> 5;
    const int lid = tid & 31;
    const int g   = lid >> 2;
    const int tig = lid & 3;
    const bool has2 = (wid < 6);

    float c[2][3][4];
    #pragma unroll
    for (int t = 0; t < 2; ++t)
        #pragma unroll
        for (int n = 0; n < 3; ++n)
            #pragma unroll
            for (int v = 0; v < 4; ++v) c[t][n][v] = 0.f;

    // precompute per-thread A staging offsets (23 float2 copies max)
    int      srcb[23];
    uint32_t dstb[23];
    #pragma unroll
    for (int k = 0; k < 23; ++k) {
        int u = tid + k * 256;
        if (u < 5832) {
            int row = u / 9;   int j   = u - row * 9;
            int ix  = row / 36; int oyz = row - ix * 36;
            int oy  = oyz / 6;  int oz  = oyz - oy * 6;
            srcb[k] = (ix * X3 + oy * X2 + oz * SX + 2 * j) * 4;
            dstb[k] = sbase + (uint32_t)(row * APITCH + 2 * j) * 4;
        } else srcb[k] = -1;
    }

    // zero both A buffers (k-pad cols, M-pad rows) and both B buffers (holes)
    for (int i = tid; i < TOTWORDS; i += 256) smem[i] = 0u;
    __syncthreads();

    const float* xb = x + (size_t)b * XB;
    const char*  xc = (const char*)xb;
    const int m0a = wid * 16, m0b = (wid + 8) * 16;

    // ---- prologue: stage iteration 0 into buffer 0 ----
    {
        #pragma unroll
        for (int k = 0; k < 23; ++k)
            if (srcb[k] >= 0) cp8(dstb[k], xc + srcb[k]);
        asm volatile("cp.async.commit_group;" ::: "memory");
        for (int t = tid; t < 507; t += 256) {
            int kx = t / 39; int r = t - kx * 39;
            int ch = r / 13; int kw = r - ch * 13;
            uint32_t val = tf32r(cw[ch * W4 + kx * W3 + kw]);   // ky=kz=0
            uint32_t* dst = smem + BBASE + kx * (24 * BPITCH) + ch * 6;
            #pragma unroll
            for (int ow = 0; ow < 6; ++ow)
                dst[(kw + ow) * BPITCH + ow] = val;
        }
    }

    #pragma unroll 1
    for (int i = 0; i < 169; ++i) {
        asm volatile("cp.async.wait_group 0;" ::: "memory");
        __syncthreads();   // A(i)/B(i) visible; compute(i-1) fully drained

        if (i < 168) {   // stage i+1 into the other buffer (overlaps compute)
            const int ni = i + 1;
            const int ky = ni / 13, kz = ni - 13 * (ni / 13);
            const int d  = (ky * X2 + kz * SX) * 4;
            const uint32_t ab = (uint32_t)((ni & 1) * ABYTES);
            #pragma unroll
            for (int k = 0; k < 23; ++k)
                if (srcb[k] >= 0) cp8(dstb[k] + ab, xc + srcb[k] + d);
            asm volatile("cp.async.commit_group;" ::: "memory");

            uint32_t* Bn = smem + BBASE + (ni & 1) * BWORDS;
            for (int t = tid; t < 507; t += 256) {
                int kx = t / 39; int r = t - kx * 39;
                int ch = r / 13; int kw = r - ch * 13;
                uint32_t val = tf32r(cw[ch * W4 + kx * W3 + ky * W2 + kz * KS + kw]);
                uint32_t* dst = Bn + kx * (24 * BPITCH) + ch * 6;
                #pragma unroll
                for (int ow = 0; ow < 6; ++ow)
                    dst[(kw + ow) * BPITCH + ow] = val;
            }
        }

        // ---- compute(i) on buffer i&1 ----
        const uint32_t* slab = smem + (i & 1) * AWORDS;
        const uint32_t* Bs   = smem + BBASE + (i & 1) * BWORDS;
        #pragma unroll 1
        for (int kx = 0; kx < 13; ++kx) {
            uint32_t bf[3][3][2];
            const uint32_t* Bk = Bs + kx * (24 * BPITCH) + (2 * tig) * BPITCH + g;
            #pragma unroll
            for (int ks = 0; ks < 3; ++ks)
                #pragma unroll
                for (int nt = 0; nt < 3; ++nt) {
                    bf[ks][nt][0] = Bk[ks * 8 * BPITCH + nt * 8];
                    bf[ks][nt][1] = Bk[ks * 8 * BPITCH + BPITCH + nt * 8];
                }
            #pragma unroll
            for (int t = 0; t < 2; ++t) {
                if (t == 1 && !has2) break;
                const int m0 = (t == 0) ? m0a : m0b;
                const uint32_t* Ar = slab + (m0 + g + 36 * kx) * APITCH + 2 * tig;
                uint2 alo[3], ahi[3];
                #pragma unroll
                for (int ks = 0; ks < 3; ++ks) {
                    alo[ks] = *(const uint2*)(Ar + ks * 8);
                    ahi[ks] = *(const uint2*)(Ar + 8 * APITCH + ks * 8);
                }
                #pragma unroll
                for (int ks = 0; ks < 3; ++ks)
                    #pragma unroll
                    for (int nt = 0; nt < 3; ++nt)
                        mma8(c[t][nt], alo[ks], ahi[ks], bf[ks][nt]);
            }
        }
    }

    // ---- epilogue: bias + ReLU + dot(lin_w) ----
    float partial = 0.f;
    #pragma unroll
    for (int t = 0; t < 2; ++t) {
        if (t == 1 && !has2) break;
        const int m0 = (t == 0) ? m0a : m0b;
        #pragma unroll
        for (int nt = 0; nt < 3; ++nt)
            #pragma unroll
            for (int v = 0; v < 4; ++v) {
                int m = m0 + g + (v >> 1) * 8;
                int n = nt * 8 + tig * 2 + (v & 1);
                if (m < 216 && n < 18) {
                    int ox = m / 36; int oyz = m - ox * 36;
                    int ch = n / 6;  int ow  = n - ch * 6;
                    float h = c[t][nt][v] + __ldg(cb + ch);
                    h = fmaxf(h, 0.f);
                    partial = fmaf(h,
                        __ldg(lw + ch * 1296 + ox * 216 + oyz * 6 + ow),
                        partial);
                }
            }
    }

    __syncthreads();              // all compute(168) slab reads done
    float* red = (float*)smem;
    red[tid] = partial;
    __syncthreads();
    if (tid < 128) red[tid] += red[tid + 128];
    __syncthreads();
    if (tid < 64)  red[tid] += red[tid + 64];
    __syncthreads();
    if (tid < 32) {
        float v = red[tid] + red[tid + 32];
        #pragma unroll
        for (int off = 16; off > 0; off >>= 1)
            v += __shfl_down_sync(0xffffffffu, v, off);
        if (tid == 0) {
            float z = v + __ldg(lb);
            out[b] = 1.f / (1.f + expf(-z));
        }
    }
}

extern "C" void kernel_launch(void* const* d_in, const int* in_sizes, int n_in,
                              void* d_out, int out_size)
{
    const float* x      = (const float*)d_in[0];
    const float* conv_w = (const float*)d_in[1];
    const float* conv_b = (const float*)d_in[2];
    const float* lin_w  = (const float*)d_in[3];
    const float* lin_b  = (const float*)d_in[4];
    float* out = (float*)d_out;

    cudaFuncSetAttribute(conv4d_mma_pipe,
                         cudaFuncAttributeMaxDynamicSharedMemorySize, SMEM_BYTES);
    conv4d_mma_pipe<<<512, 256, SMEM_BYTES>>>(x, conv_w, conv_b, lin_w, lin_b, out);
}

// round 9
// speedup vs baseline: 3.0346x; 1.3670x over previous
#include <cuda_runtime.h>
#include <cstdint>
#include <math.h>

#define SX 18
#define KS 13
#define W4 28561
#define W3 2197
#define W2 169
#define X3 5832
#define X2 324
#define XB 104976

#define APITCH 24
#define AROWS  656
#define BPITCH 28
#define AWORDS (AROWS * APITCH)               // 15744 words
#define BWORDS (13 * 24 * BPITCH)             // 9828 words
#define TOTWORDS (2 * AWORDS + 2 * BWORDS)    // 51144
#define SMEM_BYTES (TOTWORDS * 4)             // 204576 B
#define ABYTES (AWORDS * 4)
#define BBASE  (2 * AWORDS)

__device__ __forceinline__ uint32_t tf32r(float f) {
    uint32_t r; asm("cvt.rna.tf32.f32 %0, %1;" : "=r"(r) : "f"(f)); return r;
}
__device__ __forceinline__ uint32_t smem_u32(const void* p) {
    uint32_t a; asm("{ .reg .u64 t; cvta.to.shared.u64 t, %1; cvt.u32.u64 %0, t; }"
                    : "=r"(a) : "l"(p));
    return a;
}
__device__ __forceinline__ void cp8(uint32_t dst, const void* src) {
    asm volatile("cp.async.ca.shared.global [%0], [%1], 8;"
                 :: "r"(dst), "l"(src) : "memory");
}

// a0=A[g][k0], a1=A[g+8][k0], a2=A[g][k1], a3=A[g+8][k1]; k0=2tig,k1=2tig+1
// mirrored in B rows (consistent k-permutation).
__device__ __forceinline__ void mma8(float* c, uint2 alo, uint2 ahi,
                                     const uint32_t* b) {
    asm volatile(
        "mma.sync.aligned.m16n8k8.row.col.f32.tf32.tf32.f32 "
        "{%0,%1,%2,%3}, {%4,%5,%6,%7}, {%8,%9}, {%0,%1,%2,%3};"
        : "+f"(c[0]), "+f"(c[1]), "+f"(c[2]), "+f"(c[3])
        : "r"(alo.x), "r"(ahi.x), "r"(alo.y), "r"(ahi.y),
          "r"(b[0]), "r"(b[1]));
}

__global__ __launch_bounds__(256, 1)
void conv4d_mma_split(const float* __restrict__ x,  const float* __restrict__ cw,
                      const float* __restrict__ cb, const float* __restrict__ lw,
                      const float* __restrict__ lb, float* __restrict__ out)
{
    extern __shared__ uint32_t smem[];
    const uint32_t sbase = smem_u32(smem);

    const int b   = blockIdx.x;
    const int tid = threadIdx.x;
    const int wid = tid >> 5;
    const int lid = tid & 31;
    const int g   = lid >> 2;
    const int tig = lid & 3;

    // warp = (m-half, kx-group): mh owns 7 m-tiles, kg owns 4/3/3/3 kx values
    const int mh  = wid & 1;
    const int kg  = wid >> 1;
    const int kxs = (kg == 0) ? 0 : 1 + 3 * kg;     // 0,4,7,10
    const int kxe = kxs + ((kg == 0) ? 4 : 3);
    const int mbase = mh * 112;

    // C frags: 7 m-tiles x 3 n-tiles x 4 (kx-group partial sums)
    float c[7][3][4];
    #pragma unroll
    for (int t = 0; t < 7; ++t)
        #pragma unroll
        for (int n = 0; n < 3; ++n)
            #pragma unroll
            for (int v = 0; v < 4; ++v) c[t][n][v] = 0.f;

    // per-thread A staging offsets (23 float2 copies max)
    int      srcb[23];
    uint32_t dstb[23];
    #pragma unroll
    for (int k = 0; k < 23; ++k) {
        int u = tid + k * 256;
        if (u < 5832) {
            int row = u / 9;   int j   = u - row * 9;
            int ix  = row / 36; int oyz = row - ix * 36;
            int oy  = oyz / 6;  int oz  = oyz - oy * 6;
            srcb[k] = (ix * X3 + oy * X2 + oz * SX + 2 * j) * 4;
            dstb[k] = sbase + (uint32_t)(row * APITCH + 2 * j) * 4;
        } else srcb[k] = -1;
    }

    for (int i = tid; i < TOTWORDS; i += 256) smem[i] = 0u;
    __syncthreads();

    const float* xb = x + (size_t)b * XB;
    const char*  xc = (const char*)xb;

    // ---- prologue: stage iteration 0 into buffer 0 ----
    {
        #pragma unroll
        for (int k = 0; k < 23; ++k)
            if (srcb[k] >= 0) cp8(dstb[k], xc + srcb[k]);
        asm volatile("cp.async.commit_group;" ::: "memory");
        for (int t = tid; t < 507; t += 256) {
            int kx = t / 39; int r = t - kx * 39;
            int ch = r / 13; int kw = r - ch * 13;
            uint32_t val = tf32r(cw[ch * W4 + kx * W3 + kw]);   // ky=kz=0
            uint32_t* dst = smem + BBASE + kx * (24 * BPITCH) + ch * 6;
            #pragma unroll
            for (int ow = 0; ow < 6; ++ow)
                dst[(kw + ow) * BPITCH + ow] = val;
        }
    }

    #pragma unroll 1
    for (int i = 0; i < 169; ++i) {
        asm volatile("cp.async.wait_group 0;" ::: "memory");
        __syncthreads();

        if (i < 168) {
            const int ni = i + 1;
            const int ky = ni / 13, kz = ni - 13 * (ni / 13);
            const int d  = (ky * X2 + kz * SX) * 4;
            const uint32_t ab = (uint32_t)((ni & 1) * ABYTES);
            #pragma unroll
            for (int k = 0; k < 23; ++k)
                if (srcb[k] >= 0) cp8(dstb[k] + ab, xc + srcb[k] + d);
            asm volatile("cp.async.commit_group;" ::: "memory");

            uint32_t* Bn = smem + BBASE + (ni & 1) * BWORDS;
            for (int t = tid; t < 507; t += 256) {
                int kx = t / 39; int r = t - kx * 39;
                int ch = r / 13; int kw = r - ch * 13;
                uint32_t val = tf32r(cw[ch * W4 + kx * W3 + ky * W2 + kz * KS + kw]);
                uint32_t* dst = Bn + kx * (24 * BPITCH) + ch * 6;
                #pragma unroll
                for (int ow = 0; ow < 6; ++ow)
                    dst[(kw + ow) * BPITCH + ow] = val;
            }
        }

        // ---- compute(i): own kx-group x 7 m-tiles ----
        const uint32_t* slab = smem + (i & 1) * AWORDS;
        const uint32_t* Bs   = smem + BBASE + (i & 1) * BWORDS;
        #pragma unroll 1
        for (int kx = kxs; kx < kxe; ++kx) {
            uint32_t bf[3][3][2];
            const uint32_t* Bk = Bs + kx * (24 * BPITCH) + (2 * tig) * BPITCH + g;
            #pragma unroll
            for (int ks = 0; ks < 3; ++ks)
                #pragma unroll
                for (int nt = 0; nt < 3; ++nt) {
                    bf[ks][nt][0] = Bk[ks * 8 * BPITCH + nt * 8];
                    bf[ks][nt][1] = Bk[ks * 8 * BPITCH + BPITCH + nt * 8];
                }
            #pragma unroll
            for (int t = 0; t < 7; ++t) {
                const uint32_t* Ar = slab + (mbase + t * 16 + g + 36 * kx) * APITCH
                                   + 2 * tig;
                uint2 alo[3], ahi[3];
                #pragma unroll
                for (int ks = 0; ks < 3; ++ks) {
                    alo[ks] = *(const uint2*)(Ar + ks * 8);
                    ahi[ks] = *(const uint2*)(Ar + 8 * APITCH + ks * 8);
                }
                #pragma unroll
                for (int ks = 0; ks < 3; ++ks)
                    #pragma unroll
                    for (int nt = 0; nt < 3; ++nt)
                        mma8(c[t][nt], alo[ks], ahi[ks], bf[ks][nt]);
            }
        }
    }

    // ---- reduce C across the 4 kx-groups (one-time, in smem) ----
    __syncthreads();                       // all compute done; reuse buffer 0
    float* Cred = (float*)smem;            // 5376 floats
    #pragma unroll 1
    for (int ph = 0; ph < 4; ++ph) {
        if (kg == ph) {
            #pragma unroll
            for (int t = 0; t < 7; ++t)
                #pragma unroll
                for (int nt = 0; nt < 3; ++nt)
                    #pragma unroll
                    for (int v = 0; v < 4; ++v) {
                        int idx = mh * 2688 + ((t * 3 + nt) * 4 + v) * 32 + lid;
                        if (ph == 0) Cred[idx] = c[t][nt][v];
                        else         Cred[idx] += c[t][nt][v];
                    }
        }
        __syncthreads();
    }

    // ---- epilogue: all threads share the bias+ReLU+dot over 5376 elems ----
    float partial = 0.f;
    #pragma unroll 1
    for (int e = tid; e < 5376; e += 256) {
        int mh2 = e / 2688;  int r  = e - mh2 * 2688;
        int ln  = r & 31;    int q  = r >> 5;
        int v   = q & 3;     int q2 = q >> 2;
        int nt  = q2 % 3;    int t  = q2 / 3;
        int m = mh2 * 112 + t * 16 + (ln >> 2) + (v >> 1) * 8;
        int n = nt * 8 + (ln & 3) * 2 + (v & 1);
        if (m < 216 && n < 18) {
            int ox = m / 36; int oyz = m - ox * 36;
            int ch = n / 6;  int ow  = n - ch * 6;
            float h = Cred[e] + __ldg(cb + ch);
            h = fmaxf(h, 0.f);
            partial = fmaf(h, __ldg(lw + ch * 1296 + ox * 216 + oyz * 6 + ow),
                           partial);
        }
    }

    float* red = (float*)smem + 8192;      // beyond Cred region
    red[tid] = partial;
    __syncthreads();
    if (tid < 128) red[tid] += red[tid + 128];
    __syncthreads();
    if (tid < 64)  red[tid] += red[tid + 64];
    __syncthreads();
    if (tid < 32) {
        float v = red[tid] + red[tid + 32];
        #pragma unroll
        for (int off = 16; off > 0; off >>= 1)
            v += __shfl_down_sync(0xffffffffu, v, off);
        if (tid == 0) {
            float z = v + __ldg(lb);
            out[b] = 1.f / (1.f + expf(-z));
        }
    }
}

extern "C" void kernel_launch(void* const* d_in, const int* in_sizes, int n_in,
                              void* d_out, int out_size)
{
    const float* x      = (const float*)d_in[0];
    const float* conv_w = (const float*)d_in[1];
    const float* conv_b = (const float*)d_in[2];
    const float* lin_w  = (const float*)d_in[3];
    const float* lin_b  = (const float*)d_in[4];
    float* out = (float*)d_out;

    cudaFuncSetAttribute(conv4d_mma_split,
                         cudaFuncAttributeMaxDynamicSharedMemorySize, SMEM_BYTES);
    conv4d_mma_split<<<512, 256, SMEM_BYTES>>>(x, conv_w, conv_b, lin_w, lin_b, out);
}